// round 6
// baseline (speedup 1.0000x reference)
#include <cuda_runtime.h>
#include <cuda_bf16.h>
#include <cstdint>

#define BATCH 32
#define SEQ   512
#define DD    1024
#define BS_TOT (BATCH*SEQ)      // 16384
#define LDK   2048              // split row stride: hi at [0,1024), lo at [1024,2048)
#define TM    128
#define TN    128
#define KTILE 64
#define NCHUNK (DD/KTILE)       // 16
#define THREADS 512

// SMEM: per stage A(hi,lo) 32KB + B(hi,lo) 32KB = 64KB; 3 stages = 192KB
#define STAGE_BYTES 65536
#define NSTAGE 3
#define SMEM_TOTAL  (NSTAGE*STAGE_BYTES)

// ---------------- scratch (static __device__, allocation-free) ----------------
__device__ __nv_bfloat16 g_Ds [(size_t)BS_TOT * LDK];
__device__ __nv_bfloat16 g_Hs [(size_t)BS_TOT * LDK];
__device__ __nv_bfloat16 g_Ts [(size_t)BS_TOT * LDK];
__device__ __nv_bfloat16 g_Uts[(size_t)DD     * LDK];
__device__ float g_rowlin[BS_TOT];
__device__ float g_collin[BS_TOT];

// ---------------- PTX helpers (family-portable: sm_80+) ----------------
#define CP_ASYNC16(smem_u32, gptr) \
    asm volatile("cp.async.cg.shared.global [%0], [%1], 16;" :: "r"(smem_u32), "l"(gptr))
#define CP_COMMIT()  asm volatile("cp.async.commit_group;" ::: "memory")
#define CP_WAIT0()   asm volatile("cp.async.wait_group 0;" ::: "memory")
#define CP_WAIT1()   asm volatile("cp.async.wait_group 1;" ::: "memory")

#define LDSM4(r0,r1,r2,r3,addr) \
    asm volatile("ldmatrix.sync.aligned.m8n8.x4.shared.b16 {%0,%1,%2,%3}, [%4];" \
        : "=r"(r0),"=r"(r1),"=r"(r2),"=r"(r3) : "r"(addr))

#define MMA16816(d, a, b0, b1) \
    asm volatile("mma.sync.aligned.m16n8k16.row.col.f32.bf16.bf16.f32 " \
        "{%0,%1,%2,%3}, {%4,%5,%6,%7}, {%8,%9}, {%0,%1,%2,%3};" \
        : "+f"((d)[0]),"+f"((d)[1]),"+f"((d)[2]),"+f"((d)[3]) \
        : "r"((a)[0]),"r"((a)[1]),"r"((a)[2]),"r"((a)[3]),"r"((b0)),"r"((b1)))

__device__ __forceinline__ uint32_t smem_u32_of(const void* p) {
    uint32_t a;
    asm("{ .reg .u64 t; cvta.to.shared.u64 t, %1; cvt.u32.u64 %0, t; }" : "=r"(a) : "l"(p));
    return a;
}

__device__ __forceinline__ uint32_t pack_hi2(float f0, float f1,
                                             __nv_bfloat16& h0, __nv_bfloat16& h1) {
    h0 = __float2bfloat16_rn(f0);
    h1 = __float2bfloat16_rn(f1);
    return (uint32_t)__bfloat16_as_ushort(h0) | ((uint32_t)__bfloat16_as_ushort(h1) << 16);
}
__device__ __forceinline__ uint32_t pack_lo2(float f0, float f1,
                                             __nv_bfloat16 h0, __nv_bfloat16 h1) {
    __nv_bfloat16 l0 = __float2bfloat16_rn(f0 - __bfloat162float(h0));
    __nv_bfloat16 l1 = __float2bfloat16_rn(f1 - __bfloat162float(h1));
    return (uint32_t)__bfloat16_as_ushort(l0) | ((uint32_t)__bfloat16_as_ushort(l1) << 16);
}

__device__ __forceinline__ void store_split4(__nv_bfloat16* dst, float4 v) {
    __nv_bfloat16 h0, h1, h2, h3;
    uint32_t hA = pack_hi2(v.x, v.y, h0, h1);
    uint32_t hB = pack_hi2(v.z, v.w, h2, h3);
    uint32_t lA = pack_lo2(v.x, v.y, h0, h1);
    uint32_t lB = pack_lo2(v.z, v.w, h2, h3);
    *(uint2*)dst          = make_uint2(hA, hB);
    *(uint2*)(dst + 1024) = make_uint2(lA, lB);
}

// ---------------------------------------------------------------------------
// cp.async tile loader: A tile 128 rows x 64 bf16 (hi+lo), B tile same.
// SW128 swizzle: addr = row*128 + (kb ^ ((row&7)<<4)) — store & ldmatrix agree.
// ---------------------------------------------------------------------------
__device__ __forceinline__ void load_tiles(uint32_t stage_base,
    const __nv_bfloat16* __restrict__ A, const __nv_bfloat16* __restrict__ B, int c)
{
    const uint32_t sA = stage_base, sB = stage_base + 32768;
    const int tid = threadIdx.x;
    #pragma unroll
    for (int i = 0; i < 2; ++i) {
        int idx = tid + i * THREADS;          // 0..1023
        int row = idx >> 3, j = idx & 7;      // 128 rows x 8 (16B each)
        uint32_t d = (uint32_t)(row * 128 + ((j * 16) ^ ((row & 7) << 4)));
        const __nv_bfloat16* a = A + (size_t)row * LDK + c * KTILE + j * 8;
        const __nv_bfloat16* b = B + (size_t)row * LDK + c * KTILE + j * 8;
        CP_ASYNC16(sA + d,          a);
        CP_ASYNC16(sA + 16384 + d,  a + 1024);
        CP_ASYNC16(sB + d,          b);
        CP_ASYNC16(sB + 16384 + d,  b + 1024);
    }
}

// ---------------------------------------------------------------------------
// Mainloop: acc[fm][fn][4] += split(A[128xK]) * split(B[128xK])^T
// 16 warps as 4(m) x 4(n); warp tile 32m x 32n; 3 split passes (hh, lh, hl).
// 3-stage cp.async pipeline; 4 warps/SMSP hide LDSM->MMA latency.
// ---------------------------------------------------------------------------
__device__ __forceinline__ void hmma_mainloop(uint32_t smem_base,
    const __nv_bfloat16* __restrict__ Arows,
    const __nv_bfloat16* __restrict__ Brows,
    float acc[2][4][4])
{
    const int tid  = threadIdx.x;
    const int lane = tid & 31, wid = tid >> 5;
    const int wm = wid >> 2, wn = wid & 3;

    // ldmatrix per-lane address constants
    const uint32_t aOff  = (uint32_t)((wm * 32 + (lane & 15)) * 128);
    const uint32_t aKb   = (uint32_t)((lane >> 4) * 16);
    const uint32_t bOff  = (uint32_t)((wn * 32 + ((lane >> 4) << 3) + (lane & 7)) * 128);
    const uint32_t bKb   = (uint32_t)(((lane >> 3) & 1) * 16);
    const uint32_t swz   = (uint32_t)((lane & 7) << 4);

    load_tiles(smem_base,               Arows, Brows, 0); CP_COMMIT();
    load_tiles(smem_base + STAGE_BYTES, Arows, Brows, 1); CP_COMMIT();

    for (int c = 0; c < NCHUNK; ++c) {
        if (c + 1 < NCHUNK) { CP_WAIT1(); } else { CP_WAIT0(); }
        __syncthreads();                       // all warps done reading stage (c-1)%3
        if (c + 2 < NCHUNK) {                  // prefetch c+2 into stage (c+2)%3
            load_tiles(smem_base + ((c + 2) % NSTAGE) * STAGE_BYTES, Arows, Brows, c + 2);
            CP_COMMIT();
        }

        const uint32_t bufA = smem_base + (c % NSTAGE) * STAGE_BYTES;
        const uint32_t bufB = bufA + 32768;

        #pragma unroll
        for (int ks = 0; ks < 4; ++ks) {
            const uint32_t ak = (uint32_t)(ks * 32 + aKb) ^ swz;
            const uint32_t bk = (uint32_t)(ks * 32 + bKb) ^ swz;
            uint32_t ahi[2][4], alo[2][4], bhi[2][4], blo[2][4];
            #pragma unroll
            for (int fm = 0; fm < 2; ++fm) {
                uint32_t ad = bufA + aOff + fm * 2048 + ak;
                LDSM4(ahi[fm][0], ahi[fm][1], ahi[fm][2], ahi[fm][3], ad);
                LDSM4(alo[fm][0], alo[fm][1], alo[fm][2], alo[fm][3], ad + 16384);
            }
            #pragma unroll
            for (int g = 0; g < 2; ++g) {
                uint32_t bd = bufB + bOff + g * 2048 + bk;
                LDSM4(bhi[g][0], bhi[g][1], bhi[g][2], bhi[g][3], bd);
                LDSM4(blo[g][0], blo[g][1], blo[g][2], blo[g][3], bd + 16384);
            }
            #pragma unroll
            for (int fm = 0; fm < 2; ++fm) {
                #pragma unroll
                for (int fn = 0; fn < 4; ++fn) {
                    const int g = fn >> 1, p = (fn & 1) * 2;
                    MMA16816(acc[fm][fn], ahi[fm], bhi[g][p], bhi[g][p + 1]);
                    MMA16816(acc[fm][fn], alo[fm], bhi[g][p], bhi[g][p + 1]);
                    MMA16816(acc[fm][fn], ahi[fm], blo[g][p], blo[g][p + 1]);
                }
            }
        }
    }
    __syncthreads();
}

// ---------------------------------------------------------------------------
// GEMM1: T = Daug @ U; epilogue adds bias (U row 1024) and re-splits to hi/lo.
// grid: (DD/TN = 8, BS_TOT/TM = 128)
// ---------------------------------------------------------------------------
__global__ __launch_bounds__(THREADS, 1)
void gemm1_tc(const __nv_bfloat16* __restrict__ A, const __nv_bfloat16* __restrict__ B,
              const float* __restrict__ Ubias, __nv_bfloat16* __restrict__ Tout)
{
    extern __shared__ char smem[];
    uint32_t smem_base = smem_u32_of(smem);

    const size_t mBase = (size_t)blockIdx.y * TM;
    const size_t nBase = (size_t)blockIdx.x * TN;

    float acc[2][4][4] = {};
    hmma_mainloop(smem_base, A + mBase * LDK, B + nBase * LDK, acc);

    const int lane = threadIdx.x & 31, wid = threadIdx.x >> 5;
    const int wm = wid >> 2, wn = wid & 3;

    #pragma unroll
    for (int fm = 0; fm < 2; ++fm) {
        const size_t r0 = mBase + wm * 32 + fm * 16 + (lane >> 2);
        #pragma unroll
        for (int fn = 0; fn < 4; ++fn) {
            const size_t n = nBase + wn * 32 + fn * 8 + 2 * (lane & 3);
            const float b0 = Ubias[n], b1 = Ubias[n + 1];
            #pragma unroll
            for (int h = 0; h < 2; ++h) {
                const size_t r = r0 + h * 8;
                float f0 = acc[fm][fn][2 * h]     + b0;
                float f1 = acc[fm][fn][2 * h + 1] + b1;
                __nv_bfloat16 h0, h1;
                uint32_t ph = pack_hi2(f0, f1, h0, h1);
                uint32_t pl = pack_lo2(f0, f1, h0, h1);
                *(uint32_t*)(Tout + r * LDK + n)        = ph;
                *(uint32_t*)(Tout + r * LDK + 1024 + n) = pl;
            }
        }
    }
}

// ---------------------------------------------------------------------------
// GEMM2: out[b,x,y] = T[b,x,:].H[b,y,:] + rowlin[b,x] + collin[b,y]
// grid: (SEQ/TN = 4, SEQ/TM = 4, BATCH)
// ---------------------------------------------------------------------------
__global__ __launch_bounds__(THREADS, 1)
void gemm2_tc(const __nv_bfloat16* __restrict__ A, const __nv_bfloat16* __restrict__ B,
              const float* __restrict__ rowlin, const float* __restrict__ collin,
              float* __restrict__ out)
{
    extern __shared__ char smem[];
    uint32_t smem_base = smem_u32_of(smem);

    const int b = blockIdx.z;
    const size_t xBase = (size_t)blockIdx.y * TM;
    const size_t yBase = (size_t)blockIdx.x * TN;

    float acc[2][4][4] = {};
    hmma_mainloop(smem_base,
                  A + ((size_t)b * SEQ + xBase) * LDK,
                  B + ((size_t)b * SEQ + yBase) * LDK, acc);

    const int lane = threadIdx.x & 31, wid = threadIdx.x >> 5;
    const int wm = wid >> 2, wn = wid & 3;

    #pragma unroll
    for (int fm = 0; fm < 2; ++fm) {
        const size_t x0 = xBase + wm * 32 + fm * 16 + (lane >> 2);
        #pragma unroll
        for (int h = 0; h < 2; ++h) {
            const size_t gx = (size_t)b * SEQ + x0 + h * 8;
            const float rl = rowlin[gx];
            #pragma unroll
            for (int fn = 0; fn < 4; ++fn) {
                const size_t y = yBase + wn * 32 + fn * 8 + 2 * (lane & 3);
                const float c0 = collin[(size_t)b * SEQ + y];
                const float c1 = collin[(size_t)b * SEQ + y + 1];
                float2 o;
                o.x = acc[fm][fn][2 * h]     + rl + c0;
                o.y = acc[fm][fn][2 * h + 1] + rl + c1;
                *(float2*)(out + gx * SEQ + y) = o;
            }
        }
    }
}

// ---------------------------------------------------------------------------
// Fused prep: split(D) + split(H) + rowlin/collin in one pass.
// One warp per row; 2048 blocks x 256 threads (8 warps).
// ---------------------------------------------------------------------------
__global__ __launch_bounds__(256)
void prep_kernel(const float* __restrict__ D, const float* __restrict__ H,
                 const float* __restrict__ W,
                 __nv_bfloat16* __restrict__ Ds, __nv_bfloat16* __restrict__ Hs,
                 float* __restrict__ rowlin, float* __restrict__ collin)
{
    const int warp = threadIdx.x >> 5, lane = threadIdx.x & 31;
    const size_t m = (size_t)blockIdx.x * 8 + warp;
    const float* drow = D + m * DD;
    const float* hrow = H + m * DD;
    __nv_bfloat16* dd = Ds + m * LDK;
    __nv_bfloat16* dh = Hs + m * LDK;

    float s1 = 0.f, s2 = 0.f;
    #pragma unroll
    for (int i = 0; i < 8; ++i) {
        const int c = i * 128 + lane * 4;
        float4 dv = *(const float4*)(drow + c);
        float4 hv = *(const float4*)(hrow + c);
        float4 wv = *(const float4*)(W + c);              // aligned: W[0:1024]
        float w20 = __ldg(W + DD + 1 + c);
        float w21 = __ldg(W + DD + 2 + c);
        float w22 = __ldg(W + DD + 3 + c);
        float w23 = __ldg(W + DD + 4 + c);

        s1 = fmaf(dv.x, wv.x, fmaf(dv.y, wv.y, fmaf(dv.z, wv.z, fmaf(dv.w, wv.w, s1))));
        s2 = fmaf(hv.x, w20, fmaf(hv.y, w21, fmaf(hv.z, w22, fmaf(hv.w, w23, s2))));

        store_split4(dd + c, dv);
        store_split4(dh + c, hv);
    }
    #pragma unroll
    for (int o = 16; o > 0; o >>= 1) {
        s1 += __shfl_down_sync(0xffffffffu, s1, o);
        s2 += __shfl_down_sync(0xffffffffu, s2, o);
    }
    if (lane == 0) {
        rowlin[m] = s1 + W[DD];
        collin[m] = s2;
    }
}

// Transpose + split U[0:1024][1024] -> Ut_split[1024][2048]
__global__ __launch_bounds__(256)
void transU_kernel(const float* __restrict__ U, __nv_bfloat16* __restrict__ Ut)
{
    __shared__ float t[32][33];
    const int k0 = blockIdx.y * 32, n0 = blockIdx.x * 32;
    const int tx = threadIdx.x, ty = threadIdx.y;   // block (32, 8)
    #pragma unroll
    for (int i = ty; i < 32; i += 8)
        t[i][tx] = U[(size_t)(k0 + i) * DD + n0 + tx];
    __syncthreads();
    #pragma unroll
    for (int i = ty; i < 32; i += 8) {
        const size_t n = n0 + i, k = k0 + tx;
        float f = t[tx][i];
        __nv_bfloat16 h = __float2bfloat16_rn(f);
        __nv_bfloat16 l = __float2bfloat16_rn(f - __bfloat162float(h));
        Ut[n * LDK + k]        = h;
        Ut[n * LDK + 1024 + k] = l;
    }
}

// ---------------------------------------------------------------------------
extern "C" void kernel_launch(void* const* d_in, const int* in_sizes, int n_in,
                              void* d_out, int out_size)
{
    const float* D = (const float*)d_in[0];   // [32,512,1024]
    const float* H = (const float*)d_in[1];   // [32,512,1024]
    const float* U = (const float*)d_in[2];   // [1025,1024]
    const float* W = (const float*)d_in[3];   // [2049]
    float* out = (float*)d_out;               // [32,512,512]

    __nv_bfloat16 *Ds, *Hs, *Ts, *Uts;
    float *rowlin, *collin;
    cudaGetSymbolAddress((void**)&Ds,  g_Ds);
    cudaGetSymbolAddress((void**)&Hs,  g_Hs);
    cudaGetSymbolAddress((void**)&Ts,  g_Ts);
    cudaGetSymbolAddress((void**)&Uts, g_Uts);
    cudaGetSymbolAddress((void**)&rowlin, g_rowlin);
    cudaGetSymbolAddress((void**)&collin, g_collin);

    cudaFuncSetAttribute(gemm1_tc, cudaFuncAttributeMaxDynamicSharedMemorySize, SMEM_TOTAL);
    cudaFuncSetAttribute(gemm2_tc, cudaFuncAttributeMaxDynamicSharedMemorySize, SMEM_TOTAL);

    // fused prep: split(D), split(H), rowlin, collin — one pass over D and H
    prep_kernel<<<BS_TOT / 8, 256>>>(D, H, W, Ds, Hs, rowlin, collin);
    transU_kernel<<<dim3(32, 32), dim3(32, 8)>>>(U, Uts);

    // GEMM1: T = Daug @ U
    gemm1_tc<<<dim3(DD / TN, BS_TOT / TM), THREADS, SMEM_TOTAL>>>(
        Ds, Uts, U + (size_t)DD * DD, Ts);

    // GEMM2: out = T @ H^T + rowlin + collin
    gemm2_tc<<<dim3(SEQ / TN, SEQ / TM, BATCH), THREADS, SMEM_TOTAL>>>(
        Ts, Hs, rowlin, collin, out);
}

// round 7
// speedup vs baseline: 1.0635x; 1.0635x over previous
#include <cuda_runtime.h>
#include <cuda_bf16.h>
#include <cstdint>

#define BATCH 32
#define SEQ   512
#define DD    1024
#define BS_TOT (BATCH*SEQ)      // 16384
#define LDK   2048              // split row stride: hi at [0,1024), lo at [1024,2048)
#define TM    128
#define TN    256
#define KTILE 64
#define NCHUNK (DD/KTILE)       // 16
#define THREADS 256

// Stage: A_hi 16K + A_lo 16K + B_hi 32K + B_lo 32K = 96KB; 2 stages = 192KB
#define OFF_ALO 16384
#define OFF_BHI 32768
#define OFF_BLO 65536
#define STAGE_BYTES 98304
#define NSTAGE 2
#define SMEM_TOTAL (NSTAGE*STAGE_BYTES)

// ---------------- scratch (static __device__, allocation-free) ----------------
__device__ __nv_bfloat16 g_Ds [(size_t)BS_TOT * LDK];
__device__ __nv_bfloat16 g_Hs [(size_t)BS_TOT * LDK];
__device__ __nv_bfloat16 g_Ts [(size_t)BS_TOT * LDK];
__device__ __nv_bfloat16 g_Uts[(size_t)DD     * LDK];
__device__ float g_rowlin[BS_TOT];
__device__ float g_collin[BS_TOT];

// ---------------- PTX helpers (family-portable: sm_80+) ----------------
#define CP_ASYNC16(smem_u32, gptr) \
    asm volatile("cp.async.cg.shared.global [%0], [%1], 16;" :: "r"(smem_u32), "l"(gptr))
#define CP_COMMIT()  asm volatile("cp.async.commit_group;" ::: "memory")
#define CP_WAIT0()   asm volatile("cp.async.wait_group 0;" ::: "memory")
#define CP_WAIT1()   asm volatile("cp.async.wait_group 1;" ::: "memory")

#define LDSM4(r0,r1,r2,r3,addr) \
    asm volatile("ldmatrix.sync.aligned.m8n8.x4.shared.b16 {%0,%1,%2,%3}, [%4];" \
        : "=r"(r0),"=r"(r1),"=r"(r2),"=r"(r3) : "r"(addr))

#define MMA16816(d, a, b0, b1) \
    asm volatile("mma.sync.aligned.m16n8k16.row.col.f32.bf16.bf16.f32 " \
        "{%0,%1,%2,%3}, {%4,%5,%6,%7}, {%8,%9}, {%0,%1,%2,%3};" \
        : "+f"((d)[0]),"+f"((d)[1]),"+f"((d)[2]),"+f"((d)[3]) \
        : "r"((a)[0]),"r"((a)[1]),"r"((a)[2]),"r"((a)[3]),"r"((b0)),"r"((b1)))

__device__ __forceinline__ uint32_t smem_u32_of(const void* p) {
    uint32_t a;
    asm("{ .reg .u64 t; cvta.to.shared.u64 t, %1; cvt.u32.u64 %0, t; }" : "=r"(a) : "l"(p));
    return a;
}

__device__ __forceinline__ uint32_t pack_hi2(float f0, float f1,
                                             __nv_bfloat16& h0, __nv_bfloat16& h1) {
    h0 = __float2bfloat16_rn(f0);
    h1 = __float2bfloat16_rn(f1);
    return (uint32_t)__bfloat16_as_ushort(h0) | ((uint32_t)__bfloat16_as_ushort(h1) << 16);
}
__device__ __forceinline__ uint32_t pack_lo2(float f0, float f1,
                                             __nv_bfloat16 h0, __nv_bfloat16 h1) {
    __nv_bfloat16 l0 = __float2bfloat16_rn(f0 - __bfloat162float(h0));
    __nv_bfloat16 l1 = __float2bfloat16_rn(f1 - __bfloat162float(h1));
    return (uint32_t)__bfloat16_as_ushort(l0) | ((uint32_t)__bfloat16_as_ushort(l1) << 16);
}

__device__ __forceinline__ void store_split4(__nv_bfloat16* dst, float4 v) {
    __nv_bfloat16 h0, h1, h2, h3;
    uint32_t hA = pack_hi2(v.x, v.y, h0, h1);
    uint32_t hB = pack_hi2(v.z, v.w, h2, h3);
    uint32_t lA = pack_lo2(v.x, v.y, h0, h1);
    uint32_t lB = pack_lo2(v.z, v.w, h2, h3);
    *(uint2*)dst          = make_uint2(hA, hB);
    *(uint2*)(dst + 1024) = make_uint2(lA, lB);
}

// ---------------------------------------------------------------------------
// cp.async tile loader: A 128 rows, B 256 rows, each row 64 bf16 hi + 64 lo.
// SW128 swizzle: addr = row*128 + (kb ^ ((row&7)<<4)) — store & ldmatrix agree.
// ---------------------------------------------------------------------------
__device__ __forceinline__ void load_tiles(uint32_t stage_base,
    const __nv_bfloat16* __restrict__ A, const __nv_bfloat16* __restrict__ B, int c)
{
    const int tid = threadIdx.x;
    #pragma unroll
    for (int i = 0; i < 4; ++i) {            // A: 128 rows x 8 chunks, hi+lo
        int idx = tid + i * THREADS;         // 0..1023
        int row = idx >> 3, j = idx & 7;
        uint32_t d = (uint32_t)(row * 128 + ((j * 16) ^ ((row & 7) << 4)));
        const __nv_bfloat16* a = A + (size_t)row * LDK + c * KTILE + j * 8;
        CP_ASYNC16(stage_base + d,           a);
        CP_ASYNC16(stage_base + OFF_ALO + d, a + 1024);
    }
    #pragma unroll
    for (int i = 0; i < 8; ++i) {            // B: 256 rows x 8 chunks, hi+lo
        int idx = tid + i * THREADS;         // 0..2047
        int row = idx >> 3, j = idx & 7;
        uint32_t d = (uint32_t)(row * 128 + ((j * 16) ^ ((row & 7) << 4)));
        const __nv_bfloat16* b = B + (size_t)row * LDK + c * KTILE + j * 8;
        CP_ASYNC16(stage_base + OFF_BHI + d, b);
        CP_ASYNC16(stage_base + OFF_BLO + d, b + 1024);
    }
}

// ---------------------------------------------------------------------------
// Mainloop: acc[4][8][4] += split(A[128xK]) * split(B[256xK])^T
// 8 warps as 2(m) x 4(n); warp tile 64m x 64n; 3 split passes (hh, lh, hl).
// 2-stage cp.async pipeline (96KB/stage).
// ---------------------------------------------------------------------------
__device__ __forceinline__ void hmma_mainloop(uint32_t smem_base,
    const __nv_bfloat16* __restrict__ Arows,
    const __nv_bfloat16* __restrict__ Brows,
    float acc[4][8][4])
{
    const int tid  = threadIdx.x;
    const int lane = tid & 31, wid = tid >> 5;
    const int wm = wid >> 2, wn = wid & 3;

    // ldmatrix per-lane address constants
    const uint32_t aOff  = (uint32_t)((wm * 64 + (lane & 15)) * 128);
    const uint32_t aKb   = (uint32_t)((lane >> 4) * 16);
    const uint32_t bOff  = (uint32_t)((wn * 64 + ((lane >> 4) << 3) + (lane & 7)) * 128);
    const uint32_t bKb   = (uint32_t)(((lane >> 3) & 1) * 16);
    const uint32_t swz   = (uint32_t)((lane & 7) << 4);

    load_tiles(smem_base,               Arows, Brows, 0); CP_COMMIT();
    load_tiles(smem_base + STAGE_BYTES, Arows, Brows, 1); CP_COMMIT();

    for (int c = 0; c < NCHUNK; ++c) {
        if (c + 1 < NCHUNK) { CP_WAIT1(); } else { CP_WAIT0(); }
        __syncthreads();                     // chunk c resident; writers of c+1 in flight

        const uint32_t bufA = smem_base + (c & 1) * STAGE_BYTES;
        const uint32_t bufB = bufA + OFF_BHI;

        #pragma unroll
        for (int ks = 0; ks < 4; ++ks) {
            const uint32_t ak = (uint32_t)(ks * 32 + aKb) ^ swz;
            const uint32_t bk = (uint32_t)(ks * 32 + bKb) ^ swz;
            uint32_t ahi[4][4], alo[4][4], bhi[4][4], blo[4][4];
            #pragma unroll
            for (int fm = 0; fm < 4; ++fm) {
                uint32_t ad = bufA + aOff + fm * 2048 + ak;
                LDSM4(ahi[fm][0], ahi[fm][1], ahi[fm][2], ahi[fm][3], ad);
                LDSM4(alo[fm][0], alo[fm][1], alo[fm][2], alo[fm][3], ad + OFF_ALO);
            }
            #pragma unroll
            for (int g = 0; g < 4; ++g) {
                uint32_t bd = bufB + bOff + g * 2048 + bk;
                LDSM4(bhi[g][0], bhi[g][1], bhi[g][2], bhi[g][3], bd);
                LDSM4(blo[g][0], blo[g][1], blo[g][2], blo[g][3], bd + 32768);
            }
            #pragma unroll
            for (int fm = 0; fm < 4; ++fm) {
                #pragma unroll
                for (int fn = 0; fn < 8; ++fn) {
                    const int g = fn >> 1, p = (fn & 1) * 2;
                    MMA16816(acc[fm][fn], ahi[fm], bhi[g][p], bhi[g][p + 1]);
                    MMA16816(acc[fm][fn], alo[fm], bhi[g][p], bhi[g][p + 1]);
                    MMA16816(acc[fm][fn], ahi[fm], blo[g][p], blo[g][p + 1]);
                }
            }
        }
        __syncthreads();                     // all reads of stage (c&1) done
        if (c + 2 < NCHUNK) {                // now safe to overwrite with chunk c+2
            load_tiles(smem_base + (c & 1) * STAGE_BYTES, Arows, Brows, c + 2);
            CP_COMMIT();
        }
    }
}

// ---------------------------------------------------------------------------
// GEMM1: T = Daug @ U; epilogue adds bias (U row 1024) and re-splits to hi/lo.
// grid: (DD/TN = 4, BS_TOT/TM = 128)
// ---------------------------------------------------------------------------
__global__ __launch_bounds__(THREADS, 1)
void gemm1_tc(const __nv_bfloat16* __restrict__ A, const __nv_bfloat16* __restrict__ B,
              const float* __restrict__ Ubias, __nv_bfloat16* __restrict__ Tout)
{
    extern __shared__ char smem[];
    uint32_t smem_base = smem_u32_of(smem);

    const size_t mBase = (size_t)blockIdx.y * TM;
    const size_t nBase = (size_t)blockIdx.x * TN;

    float acc[4][8][4] = {};
    hmma_mainloop(smem_base, A + mBase * LDK, B + nBase * LDK, acc);

    const int lane = threadIdx.x & 31, wid = threadIdx.x >> 5;
    const int wm = wid >> 2, wn = wid & 3;

    #pragma unroll
    for (int fm = 0; fm < 4; ++fm) {
        const size_t r0 = mBase + wm * 64 + fm * 16 + (lane >> 2);
        #pragma unroll
        for (int fn = 0; fn < 8; ++fn) {
            const size_t n = nBase + wn * 64 + fn * 8 + 2 * (lane & 3);
            const float b0 = Ubias[n], b1 = Ubias[n + 1];
            #pragma unroll
            for (int h = 0; h < 2; ++h) {
                const size_t r = r0 + h * 8;
                float f0 = acc[fm][fn][2 * h]     + b0;
                float f1 = acc[fm][fn][2 * h + 1] + b1;
                __nv_bfloat16 h0, h1;
                uint32_t ph = pack_hi2(f0, f1, h0, h1);
                uint32_t pl = pack_lo2(f0, f1, h0, h1);
                *(uint32_t*)(Tout + r * LDK + n)        = ph;
                *(uint32_t*)(Tout + r * LDK + 1024 + n) = pl;
            }
        }
    }
}

// ---------------------------------------------------------------------------
// GEMM2: out[b,x,y] = T[b,x,:].H[b,y,:] + rowlin[b,x] + collin[b,y]
// grid: (SEQ/TN = 2, SEQ/TM = 4, BATCH)
// ---------------------------------------------------------------------------
__global__ __launch_bounds__(THREADS, 1)
void gemm2_tc(const __nv_bfloat16* __restrict__ A, const __nv_bfloat16* __restrict__ B,
              const float* __restrict__ rowlin, const float* __restrict__ collin,
              float* __restrict__ out)
{
    extern __shared__ char smem[];
    uint32_t smem_base = smem_u32_of(smem);

    const int b = blockIdx.z;
    const size_t xBase = (size_t)blockIdx.y * TM;
    const size_t yBase = (size_t)blockIdx.x * TN;

    float acc[4][8][4] = {};
    hmma_mainloop(smem_base,
                  A + ((size_t)b * SEQ + xBase) * LDK,
                  B + ((size_t)b * SEQ + yBase) * LDK, acc);

    const int lane = threadIdx.x & 31, wid = threadIdx.x >> 5;
    const int wm = wid >> 2, wn = wid & 3;

    #pragma unroll
    for (int fm = 0; fm < 4; ++fm) {
        const size_t x0 = xBase + wm * 64 + fm * 16 + (lane >> 2);
        #pragma unroll
        for (int h = 0; h < 2; ++h) {
            const size_t gx = (size_t)b * SEQ + x0 + h * 8;
            const float rl = rowlin[gx];
            #pragma unroll
            for (int fn = 0; fn < 8; ++fn) {
                const size_t y = yBase + wn * 64 + fn * 8 + 2 * (lane & 3);
                const float c0 = collin[(size_t)b * SEQ + y];
                const float c1 = collin[(size_t)b * SEQ + y + 1];
                float2 o;
                o.x = acc[fm][fn][2 * h]     + rl + c0;
                o.y = acc[fm][fn][2 * h + 1] + rl + c1;
                *(float2*)(out + gx * SEQ + y) = o;
            }
        }
    }
}

// ---------------------------------------------------------------------------
// Fused prep: split(D) + split(H) + rowlin/collin in one pass.
// One warp per row; 2048 blocks x 256 threads (8 warps).
// ---------------------------------------------------------------------------
__global__ __launch_bounds__(256)
void prep_kernel(const float* __restrict__ D, const float* __restrict__ H,
                 const float* __restrict__ W,
                 __nv_bfloat16* __restrict__ Ds, __nv_bfloat16* __restrict__ Hs,
                 float* __restrict__ rowlin, float* __restrict__ collin)
{
    const int warp = threadIdx.x >> 5, lane = threadIdx.x & 31;
    const size_t m = (size_t)blockIdx.x * 8 + warp;
    const float* drow = D + m * DD;
    const float* hrow = H + m * DD;
    __nv_bfloat16* dd = Ds + m * LDK;
    __nv_bfloat16* dh = Hs + m * LDK;

    float s1 = 0.f, s2 = 0.f;
    #pragma unroll
    for (int i = 0; i < 8; ++i) {
        const int c = i * 128 + lane * 4;
        float4 dv = *(const float4*)(drow + c);
        float4 hv = *(const float4*)(hrow + c);
        float4 wv = *(const float4*)(W + c);              // aligned: W[0:1024]
        float w20 = __ldg(W + DD + 1 + c);
        float w21 = __ldg(W + DD + 2 + c);
        float w22 = __ldg(W + DD + 3 + c);
        float w23 = __ldg(W + DD + 4 + c);

        s1 = fmaf(dv.x, wv.x, fmaf(dv.y, wv.y, fmaf(dv.z, wv.z, fmaf(dv.w, wv.w, s1))));
        s2 = fmaf(hv.x, w20, fmaf(hv.y, w21, fmaf(hv.z, w22, fmaf(hv.w, w23, s2))));

        store_split4(dd + c, dv);
        store_split4(dh + c, hv);
    }
    #pragma unroll
    for (int o = 16; o > 0; o >>= 1) {
        s1 += __shfl_down_sync(0xffffffffu, s1, o);
        s2 += __shfl_down_sync(0xffffffffu, s2, o);
    }
    if (lane == 0) {
        rowlin[m] = s1 + W[DD];
        collin[m] = s2;
    }
}

// Transpose + split U[0:1024][1024] -> Ut_split[1024][2048]
__global__ __launch_bounds__(256)
void transU_kernel(const float* __restrict__ U, __nv_bfloat16* __restrict__ Ut)
{
    __shared__ float t[32][33];
    const int k0 = blockIdx.y * 32, n0 = blockIdx.x * 32;
    const int tx = threadIdx.x, ty = threadIdx.y;   // block (32, 8)
    #pragma unroll
    for (int i = ty; i < 32; i += 8)
        t[i][tx] = U[(size_t)(k0 + i) * DD + n0 + tx];
    __syncthreads();
    #pragma unroll
    for (int i = ty; i < 32; i += 8) {
        const size_t n = n0 + i, k = k0 + tx;
        float f = t[tx][i];
        __nv_bfloat16 h = __float2bfloat16_rn(f);
        __nv_bfloat16 l = __float2bfloat16_rn(f - __bfloat162float(h));
        Ut[n * LDK + k]        = h;
        Ut[n * LDK + 1024 + k] = l;
    }
}

// ---------------------------------------------------------------------------
extern "C" void kernel_launch(void* const* d_in, const int* in_sizes, int n_in,
                              void* d_out, int out_size)
{
    const float* D = (const float*)d_in[0];   // [32,512,1024]
    const float* H = (const float*)d_in[1];   // [32,512,1024]
    const float* U = (const float*)d_in[2];   // [1025,1024]
    const float* W = (const float*)d_in[3];   // [2049]
    float* out = (float*)d_out;               // [32,512,512]

    __nv_bfloat16 *Ds, *Hs, *Ts, *Uts;
    float *rowlin, *collin;
    cudaGetSymbolAddress((void**)&Ds,  g_Ds);
    cudaGetSymbolAddress((void**)&Hs,  g_Hs);
    cudaGetSymbolAddress((void**)&Ts,  g_Ts);
    cudaGetSymbolAddress((void**)&Uts, g_Uts);
    cudaGetSymbolAddress((void**)&rowlin, g_rowlin);
    cudaGetSymbolAddress((void**)&collin, g_collin);

    cudaFuncSetAttribute(gemm1_tc, cudaFuncAttributeMaxDynamicSharedMemorySize, SMEM_TOTAL);
    cudaFuncSetAttribute(gemm2_tc, cudaFuncAttributeMaxDynamicSharedMemorySize, SMEM_TOTAL);

    // fused prep: split(D), split(H), rowlin, collin — one pass over D and H
    prep_kernel<<<BS_TOT / 8, 256>>>(D, H, W, Ds, Hs, rowlin, collin);
    transU_kernel<<<dim3(32, 32), dim3(32, 8)>>>(U, Uts);

    // GEMM1: T = Daug @ U      grid (4, 128)
    gemm1_tc<<<dim3(DD / TN, BS_TOT / TM), THREADS, SMEM_TOTAL>>>(
        Ds, Uts, U + (size_t)DD * DD, Ts);

    // GEMM2: out = T @ H^T + rowlin + collin   grid (2, 4, 32)
    gemm2_tc<<<dim3(SEQ / TN, SEQ / TM, BATCH), THREADS, SMEM_TOTAL>>>(
        Ts, Hs, rowlin, collin, out);
}

// round 8
// speedup vs baseline: 1.1004x; 1.0347x over previous
#include <cuda_runtime.h>
#include <cuda_bf16.h>
#include <cstdint>

#define BATCH 32
#define SEQ   512
#define DD    1024
#define BS_TOT (BATCH*SEQ)      // 16384
#define LDK   2048              // split row stride: hi at [0,1024), lo at [1024,2048)
#define TM    128
#define TN    128
#define KTILE 32
#define NCHUNK (DD/KTILE)       // 32
#define THREADS 128

// Stage: A 128 rows x 128B (hi|lo) = 16K, B same = 16K -> 32K; 3 stages = 96K
#define OFF_B       16384
#define STAGE_BYTES 32768
#define NSTAGE 3
#define SMEM_TOTAL (NSTAGE*STAGE_BYTES)   // 98304 -> 2 CTAs/SM

// ---------------- scratch (static __device__, allocation-free) ----------------
__device__ __nv_bfloat16 g_Ds [(size_t)BS_TOT * LDK];
__device__ __nv_bfloat16 g_Hs [(size_t)BS_TOT * LDK];
__device__ __nv_bfloat16 g_Ts [(size_t)BS_TOT * LDK];
__device__ __nv_bfloat16 g_Uts[(size_t)DD     * LDK];
__device__ float g_rowlin[BS_TOT];
__device__ float g_collin[BS_TOT];

// ---------------- PTX helpers (family-portable: sm_80+) ----------------
#define CP_ASYNC16(smem_u32, gptr) \
    asm volatile("cp.async.cg.shared.global [%0], [%1], 16;" :: "r"(smem_u32), "l"(gptr))
#define CP_COMMIT()  asm volatile("cp.async.commit_group;" ::: "memory")
#define CP_WAIT0()   asm volatile("cp.async.wait_group 0;" ::: "memory")
#define CP_WAIT1()   asm volatile("cp.async.wait_group 1;" ::: "memory")

#define LDSM4(r0,r1,r2,r3,addr) \
    asm volatile("ldmatrix.sync.aligned.m8n8.x4.shared.b16 {%0,%1,%2,%3}, [%4];" \
        : "=r"(r0),"=r"(r1),"=r"(r2),"=r"(r3) : "r"(addr))

#define MMA16816(d, a, b0, b1) \
    asm volatile("mma.sync.aligned.m16n8k16.row.col.f32.bf16.bf16.f32 " \
        "{%0,%1,%2,%3}, {%4,%5,%6,%7}, {%8,%9}, {%0,%1,%2,%3};" \
        : "+f"((d)[0]),"+f"((d)[1]),"+f"((d)[2]),"+f"((d)[3]) \
        : "r"((a)[0]),"r"((a)[1]),"r"((a)[2]),"r"((a)[3]),"r"((b0)),"r"((b1)))

__device__ __forceinline__ uint32_t smem_u32_of(const void* p) {
    uint32_t a;
    asm("{ .reg .u64 t; cvta.to.shared.u64 t, %1; cvt.u32.u64 %0, t; }" : "=r"(a) : "l"(p));
    return a;
}

__device__ __forceinline__ uint32_t pack_hi2(float f0, float f1,
                                             __nv_bfloat16& h0, __nv_bfloat16& h1) {
    h0 = __float2bfloat16_rn(f0);
    h1 = __float2bfloat16_rn(f1);
    return (uint32_t)__bfloat16_as_ushort(h0) | ((uint32_t)__bfloat16_as_ushort(h1) << 16);
}
__device__ __forceinline__ uint32_t pack_lo2(float f0, float f1,
                                             __nv_bfloat16 h0, __nv_bfloat16 h1) {
    __nv_bfloat16 l0 = __float2bfloat16_rn(f0 - __bfloat162float(h0));
    __nv_bfloat16 l1 = __float2bfloat16_rn(f1 - __bfloat162float(h1));
    return (uint32_t)__bfloat16_as_ushort(l0) | ((uint32_t)__bfloat16_as_ushort(l1) << 16);
}

__device__ __forceinline__ void store_split4(__nv_bfloat16* dst, float4 v) {
    __nv_bfloat16 h0, h1, h2, h3;
    uint32_t hA = pack_hi2(v.x, v.y, h0, h1);
    uint32_t hB = pack_hi2(v.z, v.w, h2, h3);
    uint32_t lA = pack_lo2(v.x, v.y, h0, h1);
    uint32_t lB = pack_lo2(v.z, v.w, h2, h3);
    *(uint2*)dst          = make_uint2(hA, hB);
    *(uint2*)(dst + 1024) = make_uint2(lA, lB);
}

// ---------------------------------------------------------------------------
// cp.async tile loader. Unified row layout: each smem row r (128B) holds
// [hi: 32 bf16 | lo: 32 bf16] for K-chunk c. SW128 swizzle on 16B chunks:
// chunk j (0..7) of row r lands at r*128 + 16*(j ^ (r&7)).
// j<4 -> hi (global col c*32 + j*8), j>=4 -> lo (global +1024 + (j-4)*8).
// ---------------------------------------------------------------------------
__device__ __forceinline__ void load_tiles(uint32_t stage_base,
    const __nv_bfloat16* __restrict__ A, const __nv_bfloat16* __restrict__ B, int c)
{
    const int tid = threadIdx.x;
    #pragma unroll
    for (int i = 0; i < 8; ++i) {            // A: 128 rows x 8 chunks
        int idx = tid + i * THREADS;         // 0..1023
        int row = idx >> 3, j = idx & 7;
        uint32_t d = (uint32_t)(row * 128 + ((j * 16) ^ ((row & 7) << 4)));
        const __nv_bfloat16* a = A + (size_t)row * LDK + c * KTILE
                                   + (j & 3) * 8 + (j >> 2) * 1024;
        CP_ASYNC16(stage_base + d, a);
    }
    #pragma unroll
    for (int i = 0; i < 8; ++i) {            // B: 128 rows x 8 chunks
        int idx = tid + i * THREADS;
        int row = idx >> 3, j = idx & 7;
        uint32_t d = (uint32_t)(row * 128 + ((j * 16) ^ ((row & 7) << 4)));
        const __nv_bfloat16* b = B + (size_t)row * LDK + c * KTILE
                                   + (j & 3) * 8 + (j >> 2) * 1024;
        CP_ASYNC16(stage_base + OFF_B + d, b);
    }
}

// ---------------------------------------------------------------------------
// Mainloop: acc[4][8][4] += split(A[128xK]) * split(B[128xK])^T
// 4 warps as 2(m) x 2(n); warp tile 64m x 64n; 3 split passes (hh, lh, hl).
// 3-stage cp.async pipeline, one barrier per chunk; 2 CTAs/SM anti-phase.
// ---------------------------------------------------------------------------
__device__ __forceinline__ void hmma_mainloop(uint32_t smem_base,
    const __nv_bfloat16* __restrict__ Arows,
    const __nv_bfloat16* __restrict__ Brows,
    float acc[4][8][4])
{
    const int tid  = threadIdx.x;
    const int lane = tid & 31, wid = tid >> 5;
    const int wm = wid >> 1, wn = wid & 1;

    // ldmatrix per-lane constants (rows are 128B: [hi 64B | lo 64B])
    const uint32_t aOff = (uint32_t)((wm * 64 + (lane & 15)) * 128);
    const uint32_t aKb  = (uint32_t)((lane >> 4) * 16);
    const uint32_t bOff = (uint32_t)((wn * 64 + ((lane >> 4) << 3) + (lane & 7)) * 128);
    const uint32_t bKb  = (uint32_t)(((lane >> 3) & 1) * 16);
    const uint32_t swz  = (uint32_t)((lane & 7) << 4);

    load_tiles(smem_base,               Arows, Brows, 0); CP_COMMIT();
    load_tiles(smem_base + STAGE_BYTES, Arows, Brows, 1); CP_COMMIT();

    for (int c = 0; c < NCHUNK; ++c) {
        if (c + 1 < NCHUNK) { CP_WAIT1(); } else { CP_WAIT0(); }
        __syncthreads();                     // readers of stage (c+2)%3 (chunk c-1) done
        if (c + 2 < NCHUNK) {
            load_tiles(smem_base + ((c + 2) % NSTAGE) * STAGE_BYTES, Arows, Brows, c + 2);
            CP_COMMIT();
        }

        const uint32_t bufA = smem_base + (c % NSTAGE) * STAGE_BYTES;
        const uint32_t bufB = bufA + OFF_B;

        #pragma unroll
        for (int ks = 0; ks < 2; ++ks) {
            const uint32_t akh = (uint32_t)(ks * 32 + aKb) ^ swz;        // hi half
            const uint32_t akl = (uint32_t)(64 + ks * 32 + aKb) ^ swz;   // lo half
            const uint32_t bkh = (uint32_t)(ks * 32 + bKb) ^ swz;
            const uint32_t bkl = (uint32_t)(64 + ks * 32 + bKb) ^ swz;
            uint32_t ahi[4][4], alo[4][4], bhi[4][4], blo[4][4];
            #pragma unroll
            for (int fm = 0; fm < 4; ++fm) {
                uint32_t ad = bufA + aOff + fm * 2048;
                LDSM4(ahi[fm][0], ahi[fm][1], ahi[fm][2], ahi[fm][3], ad + akh);
                LDSM4(alo[fm][0], alo[fm][1], alo[fm][2], alo[fm][3], ad + akl);
            }
            #pragma unroll
            for (int g = 0; g < 4; ++g) {
                uint32_t bd = bufB + bOff + g * 2048;
                LDSM4(bhi[g][0], bhi[g][1], bhi[g][2], bhi[g][3], bd + bkh);
                LDSM4(blo[g][0], blo[g][1], blo[g][2], blo[g][3], bd + bkl);
            }
            #pragma unroll
            for (int fm = 0; fm < 4; ++fm) {
                #pragma unroll
                for (int fn = 0; fn < 8; ++fn) {
                    const int g = fn >> 1, p = (fn & 1) * 2;
                    MMA16816(acc[fm][fn], ahi[fm], bhi[g][p], bhi[g][p + 1]);
                    MMA16816(acc[fm][fn], alo[fm], bhi[g][p], bhi[g][p + 1]);
                    MMA16816(acc[fm][fn], ahi[fm], blo[g][p], blo[g][p + 1]);
                }
            }
        }
    }
    __syncthreads();
}

// ---------------------------------------------------------------------------
// GEMM1: T = Daug @ U; epilogue adds bias (U row 1024) and re-splits to hi/lo.
// grid: (DD/TN = 8, BS_TOT/TM = 128)
// ---------------------------------------------------------------------------
__global__ __launch_bounds__(THREADS, 2)
void gemm1_tc(const __nv_bfloat16* __restrict__ A, const __nv_bfloat16* __restrict__ B,
              const float* __restrict__ Ubias, __nv_bfloat16* __restrict__ Tout)
{
    extern __shared__ char smem[];
    uint32_t smem_base = smem_u32_of(smem);

    const size_t mBase = (size_t)blockIdx.y * TM;
    const size_t nBase = (size_t)blockIdx.x * TN;

    float acc[4][8][4] = {};
    hmma_mainloop(smem_base, A + mBase * LDK, B + nBase * LDK, acc);

    const int lane = threadIdx.x & 31, wid = threadIdx.x >> 5;
    const int wm = wid >> 1, wn = wid & 1;

    #pragma unroll
    for (int fm = 0; fm < 4; ++fm) {
        const size_t r0 = mBase + wm * 64 + fm * 16 + (lane >> 2);
        #pragma unroll
        for (int fn = 0; fn < 8; ++fn) {
            const size_t n = nBase + wn * 64 + fn * 8 + 2 * (lane & 3);
            const float b0 = Ubias[n], b1 = Ubias[n + 1];
            #pragma unroll
            for (int h = 0; h < 2; ++h) {
                const size_t r = r0 + h * 8;
                float f0 = acc[fm][fn][2 * h]     + b0;
                float f1 = acc[fm][fn][2 * h + 1] + b1;
                __nv_bfloat16 h0, h1;
                uint32_t ph = pack_hi2(f0, f1, h0, h1);
                uint32_t pl = pack_lo2(f0, f1, h0, h1);
                *(uint32_t*)(Tout + r * LDK + n)        = ph;
                *(uint32_t*)(Tout + r * LDK + 1024 + n) = pl;
            }
        }
    }
}

// ---------------------------------------------------------------------------
// GEMM2: out[b,x,y] = T[b,x,:].H[b,y,:] + rowlin[b,x] + collin[b,y]
// grid: (SEQ/TN = 4, SEQ/TM = 4, BATCH)
// ---------------------------------------------------------------------------
__global__ __launch_bounds__(THREADS, 2)
void gemm2_tc(const __nv_bfloat16* __restrict__ A, const __nv_bfloat16* __restrict__ B,
              const float* __restrict__ rowlin, const float* __restrict__ collin,
              float* __restrict__ out)
{
    extern __shared__ char smem[];
    uint32_t smem_base = smem_u32_of(smem);

    const int b = blockIdx.z;
    const size_t xBase = (size_t)blockIdx.y * TM;
    const size_t yBase = (size_t)blockIdx.x * TN;

    float acc[4][8][4] = {};
    hmma_mainloop(smem_base,
                  A + ((size_t)b * SEQ + xBase) * LDK,
                  B + ((size_t)b * SEQ + yBase) * LDK, acc);

    const int lane = threadIdx.x & 31, wid = threadIdx.x >> 5;
    const int wm = wid >> 1, wn = wid & 1;

    #pragma unroll
    for (int fm = 0; fm < 4; ++fm) {
        const size_t x0 = xBase + wm * 64 + fm * 16 + (lane >> 2);
        #pragma unroll
        for (int h = 0; h < 2; ++h) {
            const size_t gx = (size_t)b * SEQ + x0 + h * 8;
            const float rl = rowlin[gx];
            #pragma unroll
            for (int fn = 0; fn < 8; ++fn) {
                const size_t y = yBase + wn * 64 + fn * 8 + 2 * (lane & 3);
                const float c0 = collin[(size_t)b * SEQ + y];
                const float c1 = collin[(size_t)b * SEQ + y + 1];
                float2 o;
                o.x = acc[fm][fn][2 * h]     + rl + c0;
                o.y = acc[fm][fn][2 * h + 1] + rl + c1;
                *(float2*)(out + gx * SEQ + y) = o;
            }
        }
    }
}

// ---------------------------------------------------------------------------
// Fused prep: split(D) + split(H) + rowlin/collin in one pass.
// One warp per row; 2048 blocks x 256 threads (8 warps).
// ---------------------------------------------------------------------------
__global__ __launch_bounds__(256)
void prep_kernel(const float* __restrict__ D, const float* __restrict__ H,
                 const float* __restrict__ W,
                 __nv_bfloat16* __restrict__ Ds, __nv_bfloat16* __restrict__ Hs,
                 float* __restrict__ rowlin, float* __restrict__ collin)
{
    const int warp = threadIdx.x >> 5, lane = threadIdx.x & 31;
    const size_t m = (size_t)blockIdx.x * 8 + warp;
    const float* drow = D + m * DD;
    const float* hrow = H + m * DD;
    __nv_bfloat16* dd = Ds + m * LDK;
    __nv_bfloat16* dh = Hs + m * LDK;

    float s1 = 0.f, s2 = 0.f;
    #pragma unroll
    for (int i = 0; i < 8; ++i) {
        const int c = i * 128 + lane * 4;
        float4 dv = *(const float4*)(drow + c);
        float4 hv = *(const float4*)(hrow + c);
        float4 wv = *(const float4*)(W + c);              // aligned: W[0:1024]
        float w20 = __ldg(W + DD + 1 + c);
        float w21 = __ldg(W + DD + 2 + c);
        float w22 = __ldg(W + DD + 3 + c);
        float w23 = __ldg(W + DD + 4 + c);

        s1 = fmaf(dv.x, wv.x, fmaf(dv.y, wv.y, fmaf(dv.z, wv.z, fmaf(dv.w, wv.w, s1))));
        s2 = fmaf(hv.x, w20, fmaf(hv.y, w21, fmaf(hv.z, w22, fmaf(hv.w, w23, s2))));

        store_split4(dd + c, dv);
        store_split4(dh + c, hv);
    }
    #pragma unroll
    for (int o = 16; o > 0; o >>= 1) {
        s1 += __shfl_down_sync(0xffffffffu, s1, o);
        s2 += __shfl_down_sync(0xffffffffu, s2, o);
    }
    if (lane == 0) {
        rowlin[m] = s1 + W[DD];
        collin[m] = s2;
    }
}

// Transpose + split U[0:1024][1024] -> Ut_split[1024][2048]
__global__ __launch_bounds__(256)
void transU_kernel(const float* __restrict__ U, __nv_bfloat16* __restrict__ Ut)
{
    __shared__ float t[32][33];
    const int k0 = blockIdx.y * 32, n0 = blockIdx.x * 32;
    const int tx = threadIdx.x, ty = threadIdx.y;   // block (32, 8)
    #pragma unroll
    for (int i = ty; i < 32; i += 8)
        t[i][tx] = U[(size_t)(k0 + i) * DD + n0 + tx];
    __syncthreads();
    #pragma unroll
    for (int i = ty; i < 32; i += 8) {
        const size_t n = n0 + i, k = k0 + tx;
        float f = t[tx][i];
        __nv_bfloat16 h = __float2bfloat16_rn(f);
        __nv_bfloat16 l = __float2bfloat16_rn(f - __bfloat162float(h));
        Ut[n * LDK + k]        = h;
        Ut[n * LDK + 1024 + k] = l;
    }
}

// ---------------------------------------------------------------------------
extern "C" void kernel_launch(void* const* d_in, const int* in_sizes, int n_in,
                              void* d_out, int out_size)
{
    const float* D = (const float*)d_in[0];   // [32,512,1024]
    const float* H = (const float*)d_in[1];   // [32,512,1024]
    const float* U = (const float*)d_in[2];   // [1025,1024]
    const float* W = (const float*)d_in[3];   // [2049]
    float* out = (float*)d_out;               // [32,512,512]

    __nv_bfloat16 *Ds, *Hs, *Ts, *Uts;
    float *rowlin, *collin;
    cudaGetSymbolAddress((void**)&Ds,  g_Ds);
    cudaGetSymbolAddress((void**)&Hs,  g_Hs);
    cudaGetSymbolAddress((void**)&Ts,  g_Ts);
    cudaGetSymbolAddress((void**)&Uts, g_Uts);
    cudaGetSymbolAddress((void**)&rowlin, g_rowlin);
    cudaGetSymbolAddress((void**)&collin, g_collin);

    cudaFuncSetAttribute(gemm1_tc, cudaFuncAttributeMaxDynamicSharedMemorySize, SMEM_TOTAL);
    cudaFuncSetAttribute(gemm2_tc, cudaFuncAttributeMaxDynamicSharedMemorySize, SMEM_TOTAL);

    // fused prep: split(D), split(H), rowlin, collin — one pass over D and H
    prep_kernel<<<BS_TOT / 8, 256>>>(D, H, W, Ds, Hs, rowlin, collin);
    transU_kernel<<<dim3(32, 32), dim3(32, 8)>>>(U, Uts);

    // GEMM1: T = Daug @ U      grid (8, 128)
    gemm1_tc<<<dim3(DD / TN, BS_TOT / TM), THREADS, SMEM_TOTAL>>>(
        Ds, Uts, U + (size_t)DD * DD, Ts);

    // GEMM2: out = T @ H^T + rowlin + collin   grid (4, 4, 32)
    gemm2_tc<<<dim3(SEQ / TN, SEQ / TM, BATCH), THREADS, SMEM_TOTAL>>>(
        Ts, Hs, rowlin, collin, out);
}

// round 9
// speedup vs baseline: 1.7141x; 1.5578x over previous
#include <cuda_runtime.h>
#include <cuda_fp16.h>
#include <cstdint>

#define BATCH 32
#define SEQ   512
#define DD    1024
#define BS_TOT (BATCH*SEQ)      // 16384
#define LDK   2048              // A-side split stride: hi [0,1024), lo [1024,2048)
#define LDB   1024              // B-side hi-only stride
#define TM    128
#define TN    128
#define KTILE 64
#define NCHUNK (DD/KTILE)       // 16
#define THREADS 128

// Stage: A_hi 16K + A_lo 16K + B_hi 16K = 48K; 2 stages = 96K -> 2 CTAs/SM
#define OFF_ALO 16384
#define OFF_BHI 32768
#define STAGE_BYTES 49152
#define NSTAGE 2
#define SMEM_TOTAL (NSTAGE*STAGE_BYTES)

// ---------------- scratch (static __device__, allocation-free) ----------------
__device__ __half g_Ds [(size_t)BS_TOT * LDK];   // split(D)
__device__ __half g_Hs [(size_t)BS_TOT * LDB];   // hi(H) only
__device__ __half g_Ts [(size_t)BS_TOT * LDK];   // split(T)
__device__ __half g_Uts[(size_t)DD     * LDB];   // hi(U^T) only
__device__ float g_rowlin[BS_TOT];
__device__ float g_collin[BS_TOT];

// ---------------- PTX helpers (family-portable: sm_80+) ----------------
#define CP_ASYNC16(smem_u32, gptr) \
    asm volatile("cp.async.cg.shared.global [%0], [%1], 16;" :: "r"(smem_u32), "l"(gptr))
#define CP_COMMIT()  asm volatile("cp.async.commit_group;" ::: "memory")
#define CP_WAIT0()   asm volatile("cp.async.wait_group 0;" ::: "memory")
#define CP_WAIT1()   asm volatile("cp.async.wait_group 1;" ::: "memory")

#define LDSM4(r0,r1,r2,r3,addr) \
    asm volatile("ldmatrix.sync.aligned.m8n8.x4.shared.b16 {%0,%1,%2,%3}, [%4];" \
        : "=r"(r0),"=r"(r1),"=r"(r2),"=r"(r3) : "r"(addr))

#define MMA16816(d, a, b0, b1) \
    asm volatile("mma.sync.aligned.m16n8k16.row.col.f32.f16.f16.f32 " \
        "{%0,%1,%2,%3}, {%4,%5,%6,%7}, {%8,%9}, {%0,%1,%2,%3};" \
        : "+f"((d)[0]),"+f"((d)[1]),"+f"((d)[2]),"+f"((d)[3]) \
        : "r"((a)[0]),"r"((a)[1]),"r"((a)[2]),"r"((a)[3]),"r"((b0)),"r"((b1)))

__device__ __forceinline__ uint32_t smem_u32_of(const void* p) {
    uint32_t a;
    asm("{ .reg .u64 t; cvta.to.shared.u64 t, %1; cvt.u32.u64 %0, t; }" : "=r"(a) : "l"(p));
    return a;
}

__device__ __forceinline__ uint32_t pack_hi2(float f0, float f1, __half& h0, __half& h1) {
    h0 = __float2half_rn(f0);
    h1 = __float2half_rn(f1);
    return (uint32_t)__half_as_ushort(h0) | ((uint32_t)__half_as_ushort(h1) << 16);
}
__device__ __forceinline__ uint32_t pack_lo2(float f0, float f1, __half h0, __half h1) {
    __half l0 = __float2half_rn(f0 - __half2float(h0));
    __half l1 = __float2half_rn(f1 - __half2float(h1));
    return (uint32_t)__half_as_ushort(l0) | ((uint32_t)__half_as_ushort(l1) << 16);
}

__device__ __forceinline__ void store_split4(__half* dst, float4 v) {
    __half h0, h1, h2, h3;
    uint32_t hA = pack_hi2(v.x, v.y, h0, h1);
    uint32_t hB = pack_hi2(v.z, v.w, h2, h3);
    uint32_t lA = pack_lo2(v.x, v.y, h0, h1);
    uint32_t lB = pack_lo2(v.z, v.w, h2, h3);
    *(uint2*)dst          = make_uint2(hA, hB);
    *(uint2*)(dst + 1024) = make_uint2(lA, lB);
}

__device__ __forceinline__ void store_hi4(__half* dst, float4 v) {
    __half h0, h1, h2, h3;
    uint32_t hA = pack_hi2(v.x, v.y, h0, h1);
    uint32_t hB = pack_hi2(v.z, v.w, h2, h3);
    *(uint2*)dst = make_uint2(hA, hB);
}

// ---------------------------------------------------------------------------
// cp.async tile loader: A 128 rows (hi 128B + lo 128B), B 128 rows (hi 128B).
// SW128 swizzle: 16B chunk j of row r at r*128 + 16*(j ^ (r&7)).
// ---------------------------------------------------------------------------
__device__ __forceinline__ void load_tiles(uint32_t stage_base,
    const __half* __restrict__ A, const __half* __restrict__ B, int c)
{
    const int tid = threadIdx.x;
    #pragma unroll
    for (int i = 0; i < 8; ++i) {
        int idx = tid + i * THREADS;         // 0..1023
        int row = idx >> 3, j = idx & 7;
        uint32_t d = (uint32_t)(row * 128 + ((j * 16) ^ ((row & 7) << 4)));
        const __half* a = A + (size_t)row * LDK + c * KTILE + j * 8;
        const __half* b = B + (size_t)row * LDB + c * KTILE + j * 8;
        CP_ASYNC16(stage_base + d,           a);          // A hi
        CP_ASYNC16(stage_base + OFF_ALO + d, a + 1024);   // A lo
        CP_ASYNC16(stage_base + OFF_BHI + d, b);          // B hi
    }
}

// ---------------------------------------------------------------------------
// Mainloop: acc[4][8][4] += (A_hi+A_lo)[128xK] * B_hi[128xK]^T   (2 passes)
// 4 warps as 2(m) x 2(n); warp tile 64m x 64n; 2-stage cp.async pipeline.
// ---------------------------------------------------------------------------
__device__ __forceinline__ void hmma_mainloop(uint32_t smem_base,
    const __half* __restrict__ Arows,
    const __half* __restrict__ Brows,
    float acc[4][8][4])
{
    const int tid  = threadIdx.x;
    const int lane = tid & 31, wid = tid >> 5;
    const int wm = wid >> 1, wn = wid & 1;

    // ldmatrix per-lane address constants
    const uint32_t aOff = (uint32_t)((wm * 64 + (lane & 15)) * 128);
    const uint32_t aKb  = (uint32_t)((lane >> 4) * 16);
    const uint32_t bOff = (uint32_t)((wn * 64 + ((lane >> 4) << 3) + (lane & 7)) * 128);
    const uint32_t bKb  = (uint32_t)(((lane >> 3) & 1) * 16);
    const uint32_t swz  = (uint32_t)((lane & 7) << 4);

    load_tiles(smem_base,               Arows, Brows, 0); CP_COMMIT();
    load_tiles(smem_base + STAGE_BYTES, Arows, Brows, 1); CP_COMMIT();

    for (int c = 0; c < NCHUNK; ++c) {
        if (c + 1 < NCHUNK) { CP_WAIT1(); } else { CP_WAIT0(); }
        __syncthreads();                     // chunk c resident

        const uint32_t bufA = smem_base + (c & 1) * STAGE_BYTES;
        const uint32_t bufB = bufA + OFF_BHI;

        #pragma unroll
        for (int ks = 0; ks < 4; ++ks) {
            const uint32_t ak = (uint32_t)(ks * 32 + aKb) ^ swz;
            const uint32_t bk = (uint32_t)(ks * 32 + bKb) ^ swz;
            uint32_t ahi[4][4], alo[4][4], bhi[4][4];
            #pragma unroll
            for (int fm = 0; fm < 4; ++fm) {
                uint32_t ad = bufA + aOff + fm * 2048;
                LDSM4(ahi[fm][0], ahi[fm][1], ahi[fm][2], ahi[fm][3], ad + ak);
                LDSM4(alo[fm][0], alo[fm][1], alo[fm][2], alo[fm][3], ad + OFF_ALO + ak);
            }
            #pragma unroll
            for (int g = 0; g < 4; ++g) {
                uint32_t bd = bufB + bOff + g * 2048;
                LDSM4(bhi[g][0], bhi[g][1], bhi[g][2], bhi[g][3], bd + bk);
            }
            #pragma unroll
            for (int fm = 0; fm < 4; ++fm) {
                #pragma unroll
                for (int fn = 0; fn < 8; ++fn) {
                    const int g = fn >> 1, p = (fn & 1) * 2;
                    MMA16816(acc[fm][fn], ahi[fm], bhi[g][p], bhi[g][p + 1]);
                    MMA16816(acc[fm][fn], alo[fm], bhi[g][p], bhi[g][p + 1]);
                }
            }
        }
        __syncthreads();                     // all reads of stage (c&1) done
        if (c + 2 < NCHUNK) {                // safe to overwrite with chunk c+2
            load_tiles(smem_base + (c & 1) * STAGE_BYTES, Arows, Brows, c + 2);
            CP_COMMIT();
        }
    }
}

// ---------------------------------------------------------------------------
// GEMM1: T = Daug @ U; epilogue adds bias (U row 1024) and re-splits to hi/lo.
// grid: (DD/TN = 8, BS_TOT/TM = 128)
// ---------------------------------------------------------------------------
__global__ __launch_bounds__(THREADS, 2)
void gemm1_tc(const __half* __restrict__ A, const __half* __restrict__ B,
              const float* __restrict__ Ubias, __half* __restrict__ Tout)
{
    extern __shared__ char smem[];
    uint32_t smem_base = smem_u32_of(smem);

    const size_t mBase = (size_t)blockIdx.y * TM;
    const size_t nBase = (size_t)blockIdx.x * TN;

    float acc[4][8][4] = {};
    hmma_mainloop(smem_base, A + mBase * LDK, B + nBase * LDB, acc);

    const int lane = threadIdx.x & 31, wid = threadIdx.x >> 5;
    const int wm = wid >> 1, wn = wid & 1;

    #pragma unroll
    for (int fm = 0; fm < 4; ++fm) {
        const size_t r0 = mBase + wm * 64 + fm * 16 + (lane >> 2);
        #pragma unroll
        for (int fn = 0; fn < 8; ++fn) {
            const size_t n = nBase + wn * 64 + fn * 8 + 2 * (lane & 3);
            const float b0 = Ubias[n], b1 = Ubias[n + 1];
            #pragma unroll
            for (int h = 0; h < 2; ++h) {
                const size_t r = r0 + h * 8;
                float f0 = acc[fm][fn][2 * h]     + b0;
                float f1 = acc[fm][fn][2 * h + 1] + b1;
                __half h0, h1;
                uint32_t ph = pack_hi2(f0, f1, h0, h1);
                uint32_t pl = pack_lo2(f0, f1, h0, h1);
                *(uint32_t*)(Tout + r * LDK + n)        = ph;
                *(uint32_t*)(Tout + r * LDK + 1024 + n) = pl;
            }
        }
    }
}

// ---------------------------------------------------------------------------
// GEMM2: out[b,x,y] = T[b,x,:].H[b,y,:] + rowlin[b,x] + collin[b,y]
// grid: (SEQ/TN = 4, SEQ/TM = 4, BATCH)
// ---------------------------------------------------------------------------
__global__ __launch_bounds__(THREADS, 2)
void gemm2_tc(const __half* __restrict__ A, const __half* __restrict__ B,
              const float* __restrict__ rowlin, const float* __restrict__ collin,
              float* __restrict__ out)
{
    extern __shared__ char smem[];
    uint32_t smem_base = smem_u32_of(smem);

    const int b = blockIdx.z;
    const size_t xBase = (size_t)blockIdx.y * TM;
    const size_t yBase = (size_t)blockIdx.x * TN;

    float acc[4][8][4] = {};
    hmma_mainloop(smem_base,
                  A + ((size_t)b * SEQ + xBase) * LDK,
                  B + ((size_t)b * SEQ + yBase) * LDB, acc);

    const int lane = threadIdx.x & 31, wid = threadIdx.x >> 5;
    const int wm = wid >> 1, wn = wid & 1;

    #pragma unroll
    for (int fm = 0; fm < 4; ++fm) {
        const size_t x0 = xBase + wm * 64 + fm * 16 + (lane >> 2);
        #pragma unroll
        for (int h = 0; h < 2; ++h) {
            const size_t gx = (size_t)b * SEQ + x0 + h * 8;
            const float rl = rowlin[gx];
            #pragma unroll
            for (int fn = 0; fn < 8; ++fn) {
                const size_t y = yBase + wn * 64 + fn * 8 + 2 * (lane & 3);
                const float c0 = collin[(size_t)b * SEQ + y];
                const float c1 = collin[(size_t)b * SEQ + y + 1];
                float2 o;
                o.x = acc[fm][fn][2 * h]     + rl + c0;
                o.y = acc[fm][fn][2 * h + 1] + rl + c1;
                *(float2*)(out + gx * SEQ + y) = o;
            }
        }
    }
}

// ---------------------------------------------------------------------------
// Fused prep: split(D) + hi(H) + rowlin/collin in one pass.
// One warp per row; 2048 blocks x 256 threads (8 warps).
// ---------------------------------------------------------------------------
__global__ __launch_bounds__(256)
void prep_kernel(const float* __restrict__ D, const float* __restrict__ H,
                 const float* __restrict__ W,
                 __half* __restrict__ Ds, __half* __restrict__ Hs,
                 float* __restrict__ rowlin, float* __restrict__ collin)
{
    const int warp = threadIdx.x >> 5, lane = threadIdx.x & 31;
    const size_t m = (size_t)blockIdx.x * 8 + warp;
    const float* drow = D + m * DD;
    const float* hrow = H + m * DD;
    __half* dd = Ds + m * LDK;
    __half* dh = Hs + m * LDB;

    float s1 = 0.f, s2 = 0.f;
    #pragma unroll
    for (int i = 0; i < 8; ++i) {
        const int c = i * 128 + lane * 4;
        float4 dv = *(const float4*)(drow + c);
        float4 hv = *(const float4*)(hrow + c);
        float4 wv = *(const float4*)(W + c);              // aligned: W[0:1024]
        float w20 = __ldg(W + DD + 1 + c);
        float w21 = __ldg(W + DD + 2 + c);
        float w22 = __ldg(W + DD + 3 + c);
        float w23 = __ldg(W + DD + 4 + c);

        s1 = fmaf(dv.x, wv.x, fmaf(dv.y, wv.y, fmaf(dv.z, wv.z, fmaf(dv.w, wv.w, s1))));
        s2 = fmaf(hv.x, w20, fmaf(hv.y, w21, fmaf(hv.z, w22, fmaf(hv.w, w23, s2))));

        store_split4(dd + c, dv);
        store_hi4(dh + c, hv);
    }
    #pragma unroll
    for (int o = 16; o > 0; o >>= 1) {
        s1 += __shfl_down_sync(0xffffffffu, s1, o);
        s2 += __shfl_down_sync(0xffffffffu, s2, o);
    }
    if (lane == 0) {
        rowlin[m] = s1 + W[DD];
        collin[m] = s2;
    }
}

// Transpose U[0:1024][1024] -> Ut hi-only [1024][1024]
__global__ __launch_bounds__(256)
void transU_kernel(const float* __restrict__ U, __half* __restrict__ Ut)
{
    __shared__ float t[32][33];
    const int k0 = blockIdx.y * 32, n0 = blockIdx.x * 32;
    const int tx = threadIdx.x, ty = threadIdx.y;   // block (32, 8)
    #pragma unroll
    for (int i = ty; i < 32; i += 8)
        t[i][tx] = U[(size_t)(k0 + i) * DD + n0 + tx];
    __syncthreads();
    #pragma unroll
    for (int i = ty; i < 32; i += 8) {
        const size_t n = n0 + i, k = k0 + tx;
        Ut[n * LDB + k] = __float2half_rn(t[tx][i]);
    }
}

// ---------------------------------------------------------------------------
extern "C" void kernel_launch(void* const* d_in, const int* in_sizes, int n_in,
                              void* d_out, int out_size)
{
    const float* D = (const float*)d_in[0];   // [32,512,1024]
    const float* H = (const float*)d_in[1];   // [32,512,1024]
    const float* U = (const float*)d_in[2];   // [1025,1024]
    const float* W = (const float*)d_in[3];   // [2049]
    float* out = (float*)d_out;               // [32,512,512]

    __half *Ds, *Hs, *Ts, *Uts;
    float *rowlin, *collin;
    cudaGetSymbolAddress((void**)&Ds,  g_Ds);
    cudaGetSymbolAddress((void**)&Hs,  g_Hs);
    cudaGetSymbolAddress((void**)&Ts,  g_Ts);
    cudaGetSymbolAddress((void**)&Uts, g_Uts);
    cudaGetSymbolAddress((void**)&rowlin, g_rowlin);
    cudaGetSymbolAddress((void**)&collin, g_collin);

    cudaFuncSetAttribute(gemm1_tc, cudaFuncAttributeMaxDynamicSharedMemorySize, SMEM_TOTAL);
    cudaFuncSetAttribute(gemm2_tc, cudaFuncAttributeMaxDynamicSharedMemorySize, SMEM_TOTAL);

    // fused prep: split(D), hi(H), rowlin, collin — one pass over D and H
    prep_kernel<<<BS_TOT / 8, 256>>>(D, H, W, Ds, Hs, rowlin, collin);
    transU_kernel<<<dim3(32, 32), dim3(32, 8)>>>(U, Uts);

    // GEMM1: T = Daug @ U      grid (8, 128)
    gemm1_tc<<<dim3(DD / TN, BS_TOT / TM), THREADS, SMEM_TOTAL>>>(
        Ds, Uts, U + (size_t)DD * DD, Ts);

    // GEMM2: out = T @ H^T + rowlin + collin   grid (4, 4, 32)
    gemm2_tc<<<dim3(SEQ / TN, SEQ / TM, BATCH), THREADS, SMEM_TOTAL>>>(
        Ts, Hs, rowlin, collin, out);
}

// round 10
// speedup vs baseline: 2.6196x; 1.5283x over previous
#include <cuda_runtime.h>
#include <cuda_fp16.h>
#include <cstdint>

#define BATCH 32
#define SEQ   512
#define DD    1024
#define BS_TOT (BATCH*SEQ)      // 16384
#define LD    1024              // all scratch is hi-only fp16, stride 1024
#define TM    128
#define TN    128
#define KTILE 64
#define NCHUNK (DD/KTILE)       // 16
#define THREADS 128

// Stage: A 16K + B 16K = 32K; 3 stages = 96K -> 2 CTAs/SM
#define OFF_B       16384
#define STAGE_BYTES 32768
#define NSTAGE 3
#define SMEM_TOTAL (NSTAGE*STAGE_BYTES)

// ---------------- scratch (static __device__, allocation-free) ----------------
__device__ __half g_Ds [(size_t)BS_TOT * LD];
__device__ __half g_Hs [(size_t)BS_TOT * LD];
__device__ __half g_Ts [(size_t)BS_TOT * LD];
__device__ __half g_Uts[(size_t)DD     * LD];
__device__ float g_rowlin[BS_TOT];
__device__ float g_collin[BS_TOT];

// ---------------- PTX helpers (family-portable: sm_80+) ----------------
#define CP_ASYNC16(smem_u32, gptr) \
    asm volatile("cp.async.cg.shared.global [%0], [%1], 16;" :: "r"(smem_u32), "l"(gptr))
#define CP_COMMIT()  asm volatile("cp.async.commit_group;" ::: "memory")
#define CP_WAIT0()   asm volatile("cp.async.wait_group 0;" ::: "memory")
#define CP_WAIT1()   asm volatile("cp.async.wait_group 1;" ::: "memory")

#define LDSM4(r0,r1,r2,r3,addr) \
    asm volatile("ldmatrix.sync.aligned.m8n8.x4.shared.b16 {%0,%1,%2,%3}, [%4];" \
        : "=r"(r0),"=r"(r1),"=r"(r2),"=r"(r3) : "r"(addr))

#define MMA16816(d, a, b0, b1) \
    asm volatile("mma.sync.aligned.m16n8k16.row.col.f32.f16.f16.f32 " \
        "{%0,%1,%2,%3}, {%4,%5,%6,%7}, {%8,%9}, {%0,%1,%2,%3};" \
        : "+f"((d)[0]),"+f"((d)[1]),"+f"((d)[2]),"+f"((d)[3]) \
        : "r"((a)[0]),"r"((a)[1]),"r"((a)[2]),"r"((a)[3]),"r"((b0)),"r"((b1)))

__device__ __forceinline__ uint32_t smem_u32_of(const void* p) {
    uint32_t a;
    asm("{ .reg .u64 t; cvta.to.shared.u64 t, %1; cvt.u32.u64 %0, t; }" : "=r"(a) : "l"(p));
    return a;
}

__device__ __forceinline__ uint32_t pack_h2(float f0, float f1) {
    __half h0 = __float2half_rn(f0);
    __half h1 = __float2half_rn(f1);
    return (uint32_t)__half_as_ushort(h0) | ((uint32_t)__half_as_ushort(h1) << 16);
}

__device__ __forceinline__ void store_hi4(__half* dst, float4 v) {
    *(uint2*)dst = make_uint2(pack_h2(v.x, v.y), pack_h2(v.z, v.w));
}

// ---------------------------------------------------------------------------
// cp.async tile loader: A 128 rows x 128B, B 128 rows x 128B.
// SW128 swizzle: 16B chunk j of row r at r*128 + 16*(j ^ (r&7)).
// ---------------------------------------------------------------------------
__device__ __forceinline__ void load_tiles(uint32_t stage_base,
    const __half* __restrict__ A, const __half* __restrict__ B, int c)
{
    const int tid = threadIdx.x;
    #pragma unroll
    for (int i = 0; i < 8; ++i) {
        int idx = tid + i * THREADS;         // 0..1023
        int row = idx >> 3, j = idx & 7;
        uint32_t d = (uint32_t)(row * 128 + ((j * 16) ^ ((row & 7) << 4)));
        CP_ASYNC16(stage_base + d,         A + (size_t)row * LD + c * KTILE + j * 8);
        CP_ASYNC16(stage_base + OFF_B + d, B + (size_t)row * LD + c * KTILE + j * 8);
    }
}

// ---------------------------------------------------------------------------
// Mainloop: acc[4][8][4] += A[128xK] * B[128xK]^T   (plain fp16, fp32 accum)
// 4 warps as 2(m) x 2(n); warp tile 64m x 64n; 3-stage cp.async pipeline.
// ---------------------------------------------------------------------------
__device__ __forceinline__ void hmma_mainloop(uint32_t smem_base,
    const __half* __restrict__ Arows,
    const __half* __restrict__ Brows,
    float acc[4][8][4])
{
    const int tid  = threadIdx.x;
    const int lane = tid & 31, wid = tid >> 5;
    const int wm = wid >> 1, wn = wid & 1;

    const uint32_t aOff = (uint32_t)((wm * 64 + (lane & 15)) * 128);
    const uint32_t aKb  = (uint32_t)((lane >> 4) * 16);
    const uint32_t bOff = (uint32_t)((wn * 64 + ((lane >> 4) << 3) + (lane & 7)) * 128);
    const uint32_t bKb  = (uint32_t)(((lane >> 3) & 1) * 16);
    const uint32_t swz  = (uint32_t)((lane & 7) << 4);

    load_tiles(smem_base,               Arows, Brows, 0); CP_COMMIT();
    load_tiles(smem_base + STAGE_BYTES, Arows, Brows, 1); CP_COMMIT();

    for (int c = 0; c < NCHUNK; ++c) {
        if (c + 1 < NCHUNK) { CP_WAIT1(); } else { CP_WAIT0(); }
        __syncthreads();                     // readers of stage (c+2)%3 (chunk c-1) done
        if (c + 2 < NCHUNK) {
            load_tiles(smem_base + ((c + 2) % NSTAGE) * STAGE_BYTES, Arows, Brows, c + 2);
            CP_COMMIT();
        }

        const uint32_t bufA = smem_base + (c % NSTAGE) * STAGE_BYTES;
        const uint32_t bufB = bufA + OFF_B;

        #pragma unroll
        for (int ks = 0; ks < 4; ++ks) {
            const uint32_t ak = (uint32_t)(ks * 32 + aKb) ^ swz;
            const uint32_t bk = (uint32_t)(ks * 32 + bKb) ^ swz;
            uint32_t a[4][4], b[4][4];
            #pragma unroll
            for (int fm = 0; fm < 4; ++fm) {
                uint32_t ad = bufA + aOff + fm * 2048 + ak;
                LDSM4(a[fm][0], a[fm][1], a[fm][2], a[fm][3], ad);
            }
            #pragma unroll
            for (int g = 0; g < 4; ++g) {
                uint32_t bd = bufB + bOff + g * 2048 + bk;
                LDSM4(b[g][0], b[g][1], b[g][2], b[g][3], bd);
            }
            #pragma unroll
            for (int fm = 0; fm < 4; ++fm) {
                #pragma unroll
                for (int fn = 0; fn < 8; ++fn) {
                    const int g = fn >> 1, p = (fn & 1) * 2;
                    MMA16816(acc[fm][fn], a[fm], b[g][p], b[g][p + 1]);
                }
            }
        }
    }
    __syncthreads();
}

// ---------------------------------------------------------------------------
// GEMM1: T = Daug @ U; epilogue adds bias (U row 1024), stores fp16 hi.
// grid: (DD/TN = 8, BS_TOT/TM = 128)
// ---------------------------------------------------------------------------
__global__ __launch_bounds__(THREADS, 2)
void gemm1_tc(const __half* __restrict__ A, const __half* __restrict__ B,
              const float* __restrict__ Ubias, __half* __restrict__ Tout)
{
    extern __shared__ char smem[];
    uint32_t smem_base = smem_u32_of(smem);

    const size_t mBase = (size_t)blockIdx.y * TM;
    const size_t nBase = (size_t)blockIdx.x * TN;

    float acc[4][8][4] = {};
    hmma_mainloop(smem_base, A + mBase * LD, B + nBase * LD, acc);

    const int lane = threadIdx.x & 31, wid = threadIdx.x >> 5;
    const int wm = wid >> 1, wn = wid & 1;

    #pragma unroll
    for (int fm = 0; fm < 4; ++fm) {
        const size_t r0 = mBase + wm * 64 + fm * 16 + (lane >> 2);
        #pragma unroll
        for (int fn = 0; fn < 8; ++fn) {
            const size_t n = nBase + wn * 64 + fn * 8 + 2 * (lane & 3);
            const float b0 = Ubias[n], b1 = Ubias[n + 1];
            #pragma unroll
            for (int h = 0; h < 2; ++h) {
                const size_t r = r0 + h * 8;
                *(uint32_t*)(Tout + r * LD + n) =
                    pack_h2(acc[fm][fn][2 * h] + b0, acc[fm][fn][2 * h + 1] + b1);
            }
        }
    }
}

// ---------------------------------------------------------------------------
// GEMM2: out[b,x,y] = T[b,x,:].H[b,y,:] + rowlin[b,x] + collin[b,y]
// grid: (SEQ/TN = 4, SEQ/TM = 4, BATCH)
// ---------------------------------------------------------------------------
__global__ __launch_bounds__(THREADS, 2)
void gemm2_tc(const __half* __restrict__ A, const __half* __restrict__ B,
              const float* __restrict__ rowlin, const float* __restrict__ collin,
              float* __restrict__ out)
{
    extern __shared__ char smem[];
    uint32_t smem_base = smem_u32_of(smem);

    const int b = blockIdx.z;
    const size_t xBase = (size_t)blockIdx.y * TM;
    const size_t yBase = (size_t)blockIdx.x * TN;

    float acc[4][8][4] = {};
    hmma_mainloop(smem_base,
                  A + ((size_t)b * SEQ + xBase) * LD,
                  B + ((size_t)b * SEQ + yBase) * LD, acc);

    const int lane = threadIdx.x & 31, wid = threadIdx.x >> 5;
    const int wm = wid >> 1, wn = wid & 1;

    #pragma unroll
    for (int fm = 0; fm < 4; ++fm) {
        const size_t x0 = xBase + wm * 64 + fm * 16 + (lane >> 2);
        #pragma unroll
        for (int h = 0; h < 2; ++h) {
            const size_t gx = (size_t)b * SEQ + x0 + h * 8;
            const float rl = rowlin[gx];
            #pragma unroll
            for (int fn = 0; fn < 8; ++fn) {
                const size_t y = yBase + wn * 64 + fn * 8 + 2 * (lane & 3);
                const float c0 = collin[(size_t)b * SEQ + y];
                const float c1 = collin[(size_t)b * SEQ + y + 1];
                float2 o;
                o.x = acc[fm][fn][2 * h]     + rl + c0;
                o.y = acc[fm][fn][2 * h + 1] + rl + c1;
                *(float2*)(out + gx * SEQ + y) = o;
            }
        }
    }
}

// ---------------------------------------------------------------------------
// Fused prep: hi(D) + hi(H) + rowlin/collin in one pass.
// One warp per row; 2048 blocks x 256 threads (8 warps).
// ---------------------------------------------------------------------------
__global__ __launch_bounds__(256)
void prep_kernel(const float* __restrict__ D, const float* __restrict__ H,
                 const float* __restrict__ W,
                 __half* __restrict__ Ds, __half* __restrict__ Hs,
                 float* __restrict__ rowlin, float* __restrict__ collin)
{
    const int warp = threadIdx.x >> 5, lane = threadIdx.x & 31;
    const size_t m = (size_t)blockIdx.x * 8 + warp;
    const float* drow = D + m * DD;
    const float* hrow = H + m * DD;
    __half* dd = Ds + m * LD;
    __half* dh = Hs + m * LD;

    float s1 = 0.f, s2 = 0.f;
    #pragma unroll
    for (int i = 0; i < 8; ++i) {
        const int c = i * 128 + lane * 4;
        float4 dv = *(const float4*)(drow + c);
        float4 hv = *(const float4*)(hrow + c);
        float4 wv = *(const float4*)(W + c);              // aligned: W[0:1024]
        float w20 = __ldg(W + DD + 1 + c);
        float w21 = __ldg(W + DD + 2 + c);
        float w22 = __ldg(W + DD + 3 + c);
        float w23 = __ldg(W + DD + 4 + c);

        s1 = fmaf(dv.x, wv.x, fmaf(dv.y, wv.y, fmaf(dv.z, wv.z, fmaf(dv.w, wv.w, s1))));
        s2 = fmaf(hv.x, w20, fmaf(hv.y, w21, fmaf(hv.z, w22, fmaf(hv.w, w23, s2))));

        store_hi4(dd + c, dv);
        store_hi4(dh + c, hv);
    }
    #pragma unroll
    for (int o = 16; o > 0; o >>= 1) {
        s1 += __shfl_down_sync(0xffffffffu, s1, o);
        s2 += __shfl_down_sync(0xffffffffu, s2, o);
    }
    if (lane == 0) {
        rowlin[m] = s1 + W[DD];
        collin[m] = s2;
    }
}

// Transpose U[0:1024][1024] -> Ut fp16 [1024][1024]
__global__ __launch_bounds__(256)
void transU_kernel(const float* __restrict__ U, __half* __restrict__ Ut)
{
    __shared__ float t[32][33];
    const int k0 = blockIdx.y * 32, n0 = blockIdx.x * 32;
    const int tx = threadIdx.x, ty = threadIdx.y;   // block (32, 8)
    #pragma unroll
    for (int i = ty; i < 32; i += 8)
        t[i][tx] = U[(size_t)(k0 + i) * DD + n0 + tx];
    __syncthreads();
    #pragma unroll
    for (int i = ty; i < 32; i += 8) {
        const size_t n = n0 + i, k = k0 + tx;
        Ut[n * LD + k] = __float2half_rn(t[tx][i]);
    }
}

// ---------------------------------------------------------------------------
extern "C" void kernel_launch(void* const* d_in, const int* in_sizes, int n_in,
                              void* d_out, int out_size)
{
    const float* D = (const float*)d_in[0];   // [32,512,1024]
    const float* H = (const float*)d_in[1];   // [32,512,1024]
    const float* U = (const float*)d_in[2];   // [1025,1024]
    const float* W = (const float*)d_in[3];   // [2049]
    float* out = (float*)d_out;               // [32,512,512]

    __half *Ds, *Hs, *Ts, *Uts;
    float *rowlin, *collin;
    cudaGetSymbolAddress((void**)&Ds,  g_Ds);
    cudaGetSymbolAddress((void**)&Hs,  g_Hs);
    cudaGetSymbolAddress((void**)&Ts,  g_Ts);
    cudaGetSymbolAddress((void**)&Uts, g_Uts);
    cudaGetSymbolAddress((void**)&rowlin, g_rowlin);
    cudaGetSymbolAddress((void**)&collin, g_collin);

    cudaFuncSetAttribute(gemm1_tc, cudaFuncAttributeMaxDynamicSharedMemorySize, SMEM_TOTAL);
    cudaFuncSetAttribute(gemm2_tc, cudaFuncAttributeMaxDynamicSharedMemorySize, SMEM_TOTAL);

    // fused prep: hi(D), hi(H), rowlin, collin — one pass over D and H
    prep_kernel<<<BS_TOT / 8, 256>>>(D, H, W, Ds, Hs, rowlin, collin);
    transU_kernel<<<dim3(32, 32), dim3(32, 8)>>>(U, Uts);

    // GEMM1: T = Daug @ U      grid (8, 128)
    gemm1_tc<<<dim3(DD / TN, BS_TOT / TM), THREADS, SMEM_TOTAL>>>(
        Ds, Uts, U + (size_t)DD * DD, Ts);

    // GEMM2: out = T @ H^T + rowlin + collin   grid (4, 4, 32)
    gemm2_tc<<<dim3(SEQ / TN, SEQ / TM, BATCH), THREADS, SMEM_TOTAL>>>(
        Ts, Hs, rowlin, collin, out);
}